// round 2
// baseline (speedup 1.0000x reference)
#include <cuda_runtime.h>
#include <cuda_bf16.h>

// Problem constants
#define B_  8
#define T_  32
#define S_  512
#define F_  128
#define K_  64
#define N_  200

// Tiling
#define SI  64          // s-tile
#define FI  8           // f-tile
#define TG  4           // t per register group
#define NT  128         // threads per block

// SMEM layout (bytes)
//  Vs:    K_*FI*SI floats        = 64*8*64*4   = 131072
//  attnS: K_*T_ ull (dup pairs)  = 64*32*8     = 16384
//  stg:   TG*SI*(FI+1) floats    = 4*64*9*4    = 9216
#define SMEM_VS_BYTES    (K_*FI*SI*4)
#define SMEM_ATTN_BYTES  (K_*T_*8)
#define SMEM_STG_BYTES   (TG*SI*(FI+1)*4)
#define SMEM_TOTAL       (SMEM_VS_BYTES + SMEM_ATTN_BYTES + SMEM_STG_BYTES)

// Global scratch for softmax weights, stored TRANSPOSED and DUPLICATED:
// g_attn[(b*K_ + k)*T_ + t] = (w, w)  -- so kernel B's smem load is linear.
__device__ float2 g_attn[B_ * K_ * T_];

// Packed f32x2 FMA: acc = v * a + acc  (two fp32 lanes per instruction)
__device__ __forceinline__ void fma2(unsigned long long& acc,
                                     unsigned long long v,
                                     unsigned long long a) {
    asm("fma.rn.f32x2 %0, %1, %2, %0;" : "+l"(acc) : "l"(v), "l"(a));
}

// ---------------------------------------------------------------------------
// Kernel A: gather + softmax over K. One warp per (b,t), 2 k's per lane.
// NOTE: indices are int32 (JAX x64-disabled downcasts jnp.int64 -> int32).
// ---------------------------------------------------------------------------
__global__ void attn_kernel(const float* __restrict__ corr,
                            const int* __restrict__ tIdx,
                            const int* __restrict__ rIdx) {
    int bt = blockIdx.x;            // 0..255
    int b  = bt / T_;
    int t  = bt % T_;
    int lane = threadIdx.x;         // 0..31

    int row = tIdx[bt];
    int k0 = lane;
    int k1 = lane + 32;
    float v0 = corr[row * N_ + rIdx[k0]];
    float v1 = corr[row * N_ + rIdx[k1]];

    float m = fmaxf(v0, v1);
    #pragma unroll
    for (int off = 16; off > 0; off >>= 1)
        m = fmaxf(m, __shfl_xor_sync(0xffffffffu, m, off));

    float e0 = expf(v0 - m);
    float e1 = expf(v1 - m);
    float s = e0 + e1;
    #pragma unroll
    for (int off = 16; off > 0; off >>= 1)
        s += __shfl_xor_sync(0xffffffffu, s, off);

    float inv = 1.0f / s;
    float w0 = e0 * inv;
    float w1 = e1 * inv;

    g_attn[((long)b * K_ + k0) * T_ + t] = make_float2(w0, w0);
    g_attn[((long)b * K_ + k1) * T_ + t] = make_float2(w1, w1);
}

// ---------------------------------------------------------------------------
// Kernel B: fused weighted-sum + transpose + residual add.
// Grid: (S_/SI, F_/FI, B_) = (8,16,8). Block: 128 threads.
// Each block: loads V tile [K][FI][SI] into smem once, reuses for all T=32.
// ---------------------------------------------------------------------------
__global__ void __launch_bounds__(NT, 1)
fusion_kernel(const float* __restrict__ tgt,
              const float* __restrict__ V,
              float* __restrict__ out) {
    extern __shared__ char smem[];
    float*              Vs    = (float*)smem;
    unsigned long long* attnS = (unsigned long long*)(smem + SMEM_VS_BYTES);
    float*              stg   = (float*)(smem + SMEM_VS_BYTES + SMEM_ATTN_BYTES);

    const int b  = blockIdx.z;
    const int f0 = blockIdx.y * FI;
    const int s0 = blockIdx.x * SI;
    const int tid = threadIdx.x;

    // --- load attn (duplicated pairs, already k-major in global) ---
    {
        const unsigned long long* ag =
            (const unsigned long long*)(g_attn + (long)b * K_ * T_);
        #pragma unroll
        for (int i = tid; i < K_ * T_; i += NT)
            attnS[i] = ag[i];
    }

    // --- load V tile [K][FI][SI] (float4, coalesced along s) ---
    {
        const float* Vg = V + (long)b * K_ * F_ * S_;
        #pragma unroll 4
        for (int i = tid; i < K_ * FI * (SI / 4); i += NT) {
            int k  = i / (FI * (SI / 4));
            int r  = i % (FI * (SI / 4));
            int f  = r / (SI / 4);
            int s4 = r % (SI / 4);
            float4 val = *(const float4*)(Vg + ((long)k * F_ + f0 + f) * S_ + s0 + s4 * 4);
            *(float4*)(Vs + (k * FI + f) * SI + s4 * 4) = val;
        }
    }
    __syncthreads();

    const int fl = tid / 16;   // 0..7  : f within tile
    const int sg = tid % 16;   // 0..15 : s-group, covers s = sg*4 .. sg*4+3

    for (int tg = 0; tg < T_ / TG; ++tg) {
        const int t0 = tg * TG;
        unsigned long long acc[TG][2];
        #pragma unroll
        for (int j = 0; j < TG; ++j) { acc[j][0] = 0ULL; acc[j][1] = 0ULL; }

        #pragma unroll 8
        for (int k = 0; k < K_; ++k) {
            ulonglong2 v   = *(const ulonglong2*)(Vs + (k * FI + fl) * SI + sg * 4);
            ulonglong2 a01 = *(const ulonglong2*)(attnS + k * T_ + t0);
            ulonglong2 a23 = *(const ulonglong2*)(attnS + k * T_ + t0 + 2);
            fma2(acc[0][0], v.x, a01.x); fma2(acc[0][1], v.y, a01.x);
            fma2(acc[1][0], v.x, a01.y); fma2(acc[1][1], v.y, a01.y);
            fma2(acc[2][0], v.x, a23.x); fma2(acc[2][1], v.y, a23.x);
            fma2(acc[3][0], v.x, a23.y); fma2(acc[3][1], v.y, a23.y);
        }

        // --- stage to smem [t][s][f] (pad f-dim to FI+1 for banks) ---
        #pragma unroll
        for (int j = 0; j < TG; ++j) {
            #pragma unroll
            for (int p = 0; p < 2; ++p) {
                unsigned long long a = acc[j][p];
                float lo = __uint_as_float((unsigned)(a & 0xffffffffULL));
                float hi = __uint_as_float((unsigned)(a >> 32));
                int s = sg * 4 + p * 2;
                stg[(j * SI + s)     * (FI + 1) + fl] = lo;
                stg[(j * SI + s + 1) * (FI + 1) + fl] = hi;
            }
        }
        __syncthreads();

        // --- coalesced epilogue: f fastest -> full 32B sectors ---
        #pragma unroll
        for (int i = tid; i < TG * SI * FI; i += NT) {
            int f = i % FI;
            int s = (i / FI) % SI;
            int t = i / (FI * SI);
            float c = stg[(t * SI + s) * (FI + 1) + f];
            long gi = ((((long)b * T_ + t0 + t) * S_ + s0 + s)) * F_ + f0 + f;
            out[gi] = tgt[gi] + c;
        }
        __syncthreads();
    }
}

// ---------------------------------------------------------------------------
extern "C" void kernel_launch(void* const* d_in, const int* in_sizes, int n_in,
                              void* d_out, int out_size) {
    const float* tgt  = nullptr;   // 16777216
    const float* V    = nullptr;   // 33554432
    const float* corr = nullptr;   // 40000
    const int*   tIdx = nullptr;   // 256   (int32! jax x64 disabled)
    const int*   rIdx = nullptr;   // 64    (int32!)

    for (int i = 0; i < n_in; ++i) {
        switch (in_sizes[i]) {
            case 16777216: tgt  = (const float*)d_in[i]; break;
            case 33554432: V    = (const float*)d_in[i]; break;
            case 40000:    corr = (const float*)d_in[i]; break;
            case 256:      tIdx = (const int*)d_in[i]; break;
            case 64:       rIdx = (const int*)d_in[i]; break;
            default: break;
        }
    }

    cudaFuncSetAttribute(fusion_kernel,
                         cudaFuncAttributeMaxDynamicSharedMemorySize,
                         SMEM_TOTAL);

    attn_kernel<<<B_ * T_, 32>>>(corr, tIdx, rIdx);

    dim3 grid(S_ / SI, F_ / FI, B_);
    fusion_kernel<<<grid, NT, SMEM_TOTAL>>>(tgt, V, (float*)d_out);
}

// round 3
// speedup vs baseline: 1.4586x; 1.4586x over previous
#include <cuda_runtime.h>
#include <cuda_bf16.h>

// Problem constants
#define B_  8
#define T_  32
#define S_  512
#define F_  128
#define K_  64
#define N_  200

// Tiling
#define SI  64          // s-tile
#define FI  8           // f-tile
#define TG  8           // t's per thread in the FMA loop
#define NT  512         // threads per block (16 warps)

// SMEM layout (bytes)
//  Vs:    K_*FI*SI floats          = 131072
//  attnS: K_*T_ ull (dup pairs)    = 16384
//  stg:   T_*SI*(FI+1) floats      = 73728
#define SMEM_VS_BYTES    (K_*FI*SI*4)
#define SMEM_ATTN_BYTES  (K_*T_*8)
#define SMEM_STG_BYTES   (T_*SI*(FI+1)*4)
#define SMEM_TOTAL       (SMEM_VS_BYTES + SMEM_ATTN_BYTES + SMEM_STG_BYTES)

// Packed f32x2 FMA: acc = v * a + acc
__device__ __forceinline__ void fma2(unsigned long long& acc,
                                     unsigned long long v,
                                     unsigned long long a) {
    asm("fma.rn.f32x2 %0, %1, %2, %0;" : "+l"(acc) : "l"(v), "l"(a));
}

// ---------------------------------------------------------------------------
// Single fused kernel: softmax (recomputed per block, tiny) + weighted sum +
// transpose + residual add.
// Grid: (S_/SI, F_/FI, B_) = (8,16,8) = 1024 blocks. Block: 512 threads.
// Each block holds V tile [K][FI][SI] in smem, reused for all T=32 targets.
// ---------------------------------------------------------------------------
__global__ void __launch_bounds__(NT, 1)
fusion_kernel(const float* __restrict__ tgt,
              const float* __restrict__ V,
              const float* __restrict__ corr,
              const int*   __restrict__ tIdx,
              const int*   __restrict__ rIdx,
              float* __restrict__ out) {
    extern __shared__ char smem[];
    float*              Vs    = (float*)smem;
    unsigned long long* attnS = (unsigned long long*)(smem + SMEM_VS_BYTES);
    float*              stg   = (float*)(smem + SMEM_VS_BYTES + SMEM_ATTN_BYTES);

    const int b   = blockIdx.z;
    const int f0  = blockIdx.y * FI;
    const int s0  = blockIdx.x * SI;
    const int tid = threadIdx.x;
    const int wid  = tid >> 5;
    const int lane = tid & 31;

    // --- softmax: each of 16 warps handles 2 t's (gather from L2-hot corr) ---
    {
        int c0 = rIdx[lane];
        int c1 = rIdx[lane + 32];
        #pragma unroll
        for (int t = wid; t < T_; t += 16) {
            int row = tIdx[b * T_ + t];
            float v0 = __ldg(corr + row * N_ + c0);
            float v1 = __ldg(corr + row * N_ + c1);
            float m = fmaxf(v0, v1);
            #pragma unroll
            for (int off = 16; off > 0; off >>= 1)
                m = fmaxf(m, __shfl_xor_sync(0xffffffffu, m, off));
            float e0 = expf(v0 - m);
            float e1 = expf(v1 - m);
            float s = e0 + e1;
            #pragma unroll
            for (int off = 16; off > 0; off >>= 1)
                s += __shfl_xor_sync(0xffffffffu, s, off);
            float inv = 1.0f / s;
            unsigned w0 = __float_as_uint(e0 * inv);
            unsigned w1 = __float_as_uint(e1 * inv);
            attnS[lane * T_ + t]        = ((unsigned long long)w0 << 32) | w0;
            attnS[(lane + 32) * T_ + t] = ((unsigned long long)w1 << 32) | w1;
        }
    }

    // --- load V tile [K][FI][SI] (float4, coalesced along s) ---
    {
        const float* Vg = V + (long)b * K_ * F_ * S_;
        #pragma unroll
        for (int i = tid; i < K_ * FI * (SI / 4); i += NT) {
            int k  = i / (FI * (SI / 4));
            int r  = i % (FI * (SI / 4));
            int f  = r / (SI / 4);
            int s4 = r % (SI / 4);
            float4 val = *(const float4*)(Vg + ((long)k * F_ + f0 + f) * S_ + s0 + s4 * 4);
            *(float4*)(Vs + (k * FI + f) * SI + s4 * 4) = val;
        }
    }
    __syncthreads();

    // --- main FMA loop: thread (tq, fl, sg) accumulates 8 t x 4 s x 1 f ---
    const int sg = tid & 15;          // 0..15 : s-group (4 s each)
    const int fl = (tid >> 4) & 7;    // 0..7  : f within tile
    const int tq = tid >> 7;          // 0..3  : t-quadrant
    const int t0 = tq * TG;

    unsigned long long acc[TG][2];
    #pragma unroll
    for (int j = 0; j < TG; ++j) { acc[j][0] = 0ULL; acc[j][1] = 0ULL; }

    #pragma unroll 8
    for (int k = 0; k < K_; ++k) {
        ulonglong2 v = *(const ulonglong2*)(Vs + (k * FI + fl) * SI + sg * 4);
        ulonglong2 a01 = *(const ulonglong2*)(attnS + k * T_ + t0);
        ulonglong2 a23 = *(const ulonglong2*)(attnS + k * T_ + t0 + 2);
        ulonglong2 a45 = *(const ulonglong2*)(attnS + k * T_ + t0 + 4);
        ulonglong2 a67 = *(const ulonglong2*)(attnS + k * T_ + t0 + 6);
        fma2(acc[0][0], v.x, a01.x); fma2(acc[0][1], v.y, a01.x);
        fma2(acc[1][0], v.x, a01.y); fma2(acc[1][1], v.y, a01.y);
        fma2(acc[2][0], v.x, a23.x); fma2(acc[2][1], v.y, a23.x);
        fma2(acc[3][0], v.x, a23.y); fma2(acc[3][1], v.y, a23.y);
        fma2(acc[4][0], v.x, a45.x); fma2(acc[4][1], v.y, a45.x);
        fma2(acc[5][0], v.x, a45.y); fma2(acc[5][1], v.y, a45.y);
        fma2(acc[6][0], v.x, a67.x); fma2(acc[6][1], v.y, a67.x);
        fma2(acc[7][0], v.x, a67.y); fma2(acc[7][1], v.y, a67.y);
    }

    // --- stage to smem [t][s][f] (pad f-dim to FI+1 for banks) ---
    __syncthreads();   // Vs no longer needed; stg overlaps nothing, but order writes
    #pragma unroll
    for (int j = 0; j < TG; ++j) {
        #pragma unroll
        for (int p = 0; p < 2; ++p) {
            unsigned long long a = acc[j][p];
            float lo = __uint_as_float((unsigned)(a & 0xffffffffULL));
            float hi = __uint_as_float((unsigned)(a >> 32));
            int s = sg * 4 + p * 2;
            stg[((t0 + j) * SI + s)     * (FI + 1) + fl] = lo;
            stg[((t0 + j) * SI + s + 1) * (FI + 1) + fl] = hi;
        }
    }
    __syncthreads();

    // --- coalesced epilogue: f fastest -> full 32B sectors ---
    #pragma unroll
    for (int i = tid; i < T_ * SI * FI; i += NT) {
        int f = i % FI;
        int s = (i / FI) % SI;
        int t = i / (FI * SI);
        float c = stg[(t * SI + s) * (FI + 1) + f];
        long gi = (((long)b * T_ + t) * S_ + s0 + s) * F_ + f0 + f;
        out[gi] = tgt[gi] + c;
    }
}

// ---------------------------------------------------------------------------
extern "C" void kernel_launch(void* const* d_in, const int* in_sizes, int n_in,
                              void* d_out, int out_size) {
    const float* tgt  = nullptr;   // 16777216
    const float* V    = nullptr;   // 33554432
    const float* corr = nullptr;   // 40000
    const int*   tIdx = nullptr;   // 256   (int32: jax x64 disabled)
    const int*   rIdx = nullptr;   // 64

    for (int i = 0; i < n_in; ++i) {
        switch (in_sizes[i]) {
            case 16777216: tgt  = (const float*)d_in[i]; break;
            case 33554432: V    = (const float*)d_in[i]; break;
            case 40000:    corr = (const float*)d_in[i]; break;
            case 256:      tIdx = (const int*)d_in[i]; break;
            case 64:       rIdx = (const int*)d_in[i]; break;
            default: break;
        }
    }

    cudaFuncSetAttribute(fusion_kernel,
                         cudaFuncAttributeMaxDynamicSharedMemorySize,
                         SMEM_TOTAL);

    dim3 grid(S_ / SI, F_ / FI, B_);
    fusion_kernel<<<grid, NT, SMEM_TOTAL>>>(tgt, V, corr, tIdx, rIdx, (float*)d_out);
}

// round 4
// speedup vs baseline: 1.7753x; 1.2172x over previous
#include <cuda_runtime.h>
#include <cuda_bf16.h>

// Problem constants
#define B_  8
#define T_  32
#define S_  512
#define F_  128
#define K_  64
#define N_  200

// Tiling
#define SI  32          // s-tile
#define FI  8           // f-tile
#define TG  8           // t's per thread in the FMA loop
#define NT  256         // threads per block (8 warps)

// SMEM (bytes):
//   Vs:    K*FI*SI floats  = 65536   (staging buffer overlays this after FMA loop)
//   attnF: K*T floats      = 8192    (non-duplicated weights)
//   stg:   T*SI*(FI+1)*4   = 36864   <= 65536, overlays Vs
#define SMEM_VS_BYTES    (K_*FI*SI*4)
#define SMEM_ATTN_BYTES  (K_*T_*4)
#define SMEM_TOTAL       (SMEM_VS_BYTES + SMEM_ATTN_BYTES)

// Packed f32x2 FMA: acc = v * a + acc
__device__ __forceinline__ void fma2(unsigned long long& acc,
                                     unsigned long long v,
                                     unsigned long long a) {
    asm("fma.rn.f32x2 %0, %1, %2, %0;" : "+l"(acc) : "l"(v), "l"(a));
}
// Duplicate one fp32 into both lanes of an f32x2 register pair (alu pipe).
__device__ __forceinline__ unsigned long long dup2(float w) {
    unsigned long long r;
    asm("mov.b64 %0, {%1, %1};" : "=l"(r) : "f"(w));
    return r;
}

// ---------------------------------------------------------------------------
// Fused kernel: softmax (recomputed per block) + weighted sum + transpose +
// residual add. Grid: (S/SI, F/FI, B) = (16,16,8) = 2048 blocks, 256 thr.
// 72KB smem -> 3 CTAs/SM resident: memory phases of one CTA overlap the
// FMA phase of another.
// ---------------------------------------------------------------------------
__global__ void __launch_bounds__(NT, 3)
fusion_kernel(const float* __restrict__ tgt,
              const float* __restrict__ V,
              const float* __restrict__ corr,
              const int*   __restrict__ tIdx,
              const int*   __restrict__ rIdx,
              float* __restrict__ out) {
    extern __shared__ char smem[];
    float* Vs    = (float*)smem;                           // [K][FI][SI]
    float* stg   = (float*)smem;                           // overlays Vs later
    float* attnF = (float*)(smem + SMEM_VS_BYTES);         // [K][T]

    const int b   = blockIdx.z;
    const int f0  = blockIdx.y * FI;
    const int s0  = blockIdx.x * SI;
    const int tid = threadIdx.x;
    const int wid  = tid >> 5;
    const int lane = tid & 31;

    // --- softmax: 8 warps x 4 t's each, gather from L2-hot corr ---
    {
        int c0 = rIdx[lane];
        int c1 = rIdx[lane + 32];
        #pragma unroll
        for (int t = wid; t < T_; t += (NT / 32)) {
            int row = tIdx[b * T_ + t];
            float v0 = __ldg(corr + row * N_ + c0);
            float v1 = __ldg(corr + row * N_ + c1);
            float m = fmaxf(v0, v1);
            #pragma unroll
            for (int off = 16; off > 0; off >>= 1)
                m = fmaxf(m, __shfl_xor_sync(0xffffffffu, m, off));
            float e0 = expf(v0 - m);
            float e1 = expf(v1 - m);
            float s = e0 + e1;
            #pragma unroll
            for (int off = 16; off > 0; off >>= 1)
                s += __shfl_xor_sync(0xffffffffu, s, off);
            float inv = 1.0f / s;
            attnF[lane * T_ + t]        = e0 * inv;
            attnF[(lane + 32) * T_ + t] = e1 * inv;
        }
    }

    // --- load V tile [K][FI][SI] (float4, coalesced along s) ---
    {
        const float* Vg = V + (long)b * K_ * F_ * S_;
        #pragma unroll
        for (int i = tid; i < K_ * FI * (SI / 4); i += NT) {
            int k  = i / (FI * (SI / 4));
            int r  = i % (FI * (SI / 4));
            int f  = r / (SI / 4);
            int s4 = r % (SI / 4);
            float4 val = *(const float4*)(Vg + ((long)k * F_ + f0 + f) * S_ + s0 + s4 * 4);
            *(float4*)(Vs + (k * FI + f) * SI + s4 * 4) = val;
        }
    }
    __syncthreads();

    // --- main FMA loop: thread (tq, fl, sg) accumulates 8 t x 4 s x 1 f ---
    const int sg = tid & 7;           // 0..7 : s-group (4 s each)
    const int fl = (tid >> 3) & 7;    // 0..7 : f within tile
    const int tq = tid >> 6;          // 0..3 : t-quadrant
    const int t0 = tq * TG;

    unsigned long long acc[TG][2];
    #pragma unroll
    for (int j = 0; j < TG; ++j) { acc[j][0] = 0ULL; acc[j][1] = 0ULL; }

    #pragma unroll 4
    for (int k = 0; k < K_; ++k) {
        ulonglong2 v  = *(const ulonglong2*)(Vs + (k * FI + fl) * SI + sg * 4);
        float4 wlo = *(const float4*)(attnF + k * T_ + t0);      // broadcast
        float4 whi = *(const float4*)(attnF + k * T_ + t0 + 4);  // broadcast
        unsigned long long a0 = dup2(wlo.x), a1 = dup2(wlo.y);
        unsigned long long a2 = dup2(wlo.z), a3 = dup2(wlo.w);
        unsigned long long a4 = dup2(whi.x), a5 = dup2(whi.y);
        unsigned long long a6 = dup2(whi.z), a7 = dup2(whi.w);
        fma2(acc[0][0], v.x, a0); fma2(acc[0][1], v.y, a0);
        fma2(acc[1][0], v.x, a1); fma2(acc[1][1], v.y, a1);
        fma2(acc[2][0], v.x, a2); fma2(acc[2][1], v.y, a2);
        fma2(acc[3][0], v.x, a3); fma2(acc[3][1], v.y, a3);
        fma2(acc[4][0], v.x, a4); fma2(acc[4][1], v.y, a4);
        fma2(acc[5][0], v.x, a5); fma2(acc[5][1], v.y, a5);
        fma2(acc[6][0], v.x, a6); fma2(acc[6][1], v.y, a6);
        fma2(acc[7][0], v.x, a7); fma2(acc[7][1], v.y, a7);
    }

    // --- stage to smem [t][s][FI+1] (overlays Vs; dead after loop) ---
    __syncthreads();
    #pragma unroll
    for (int j = 0; j < TG; ++j) {
        #pragma unroll
        for (int p = 0; p < 2; ++p) {
            unsigned long long a = acc[j][p];
            float lo = __uint_as_float((unsigned)(a & 0xffffffffULL));
            float hi = __uint_as_float((unsigned)(a >> 32));
            int s = sg * 4 + p * 2;
            stg[((t0 + j) * SI + s)     * (FI + 1) + fl] = lo;
            stg[((t0 + j) * SI + s + 1) * (FI + 1) + fl] = hi;
        }
    }
    __syncthreads();

    // --- coalesced epilogue: f fastest -> full 32B sectors ---
    #pragma unroll
    for (int i = tid; i < T_ * SI * FI; i += NT) {
        int f = i & (FI - 1);
        int s = (i >> 3) & (SI - 1);
        int t = i >> 8;
        float c = stg[(t * SI + s) * (FI + 1) + f];
        long gi = (((long)b * T_ + t) * S_ + s0 + s) * F_ + f0 + f;
        out[gi] = tgt[gi] + c;
    }
}

// ---------------------------------------------------------------------------
extern "C" void kernel_launch(void* const* d_in, const int* in_sizes, int n_in,
                              void* d_out, int out_size) {
    const float* tgt  = nullptr;   // 16777216
    const float* V    = nullptr;   // 33554432
    const float* corr = nullptr;   // 40000
    const int*   tIdx = nullptr;   // 256   (int32: jax x64 disabled)
    const int*   rIdx = nullptr;   // 64

    for (int i = 0; i < n_in; ++i) {
        switch (in_sizes[i]) {
            case 16777216: tgt  = (const float*)d_in[i]; break;
            case 33554432: V    = (const float*)d_in[i]; break;
            case 40000:    corr = (const float*)d_in[i]; break;
            case 256:      tIdx = (const int*)d_in[i]; break;
            case 64:       rIdx = (const int*)d_in[i]; break;
            default: break;
        }
    }

    cudaFuncSetAttribute(fusion_kernel,
                         cudaFuncAttributeMaxDynamicSharedMemorySize,
                         SMEM_TOTAL);

    dim3 grid(S_ / SI, F_ / FI, B_);
    fusion_kernel<<<grid, NT, SMEM_TOTAL>>>(tgt, V, corr, tIdx, rIdx, (float*)d_out);
}

// round 5
// speedup vs baseline: 2.2277x; 1.2548x over previous
#include <cuda_runtime.h>
#include <cuda_bf16.h>

// Problem constants
#define B_  8
#define T_  32
#define S_  512
#define F_  128
#define K_  64
#define N_  200

// Tiling
#define SI  32          // s-tile
#define FI  8           // f-tile
#define TG  8           // t's per thread in the FMA loop
#define NT  256         // threads per block (8 warps)
#define KC  16          // k's per pipeline chunk
#define NCHUNK (K_/KC)  // 4

// SMEM (bytes):
//   Vbuf: 2 x KC*FI*SI floats = 2 x 16384 = 32768  (double buffer)
//   attnF: K*T floats         = 8192
//   stg:  T*SI*(FI+1)*4       = 36864  -> overlays Vbuf+part of attn region
#define SMEM_VBUF_BYTES  (KC*FI*SI*4)
#define SMEM_ATTN_BYTES  (K_*T_*4)
#define SMEM_TOTAL       (2*SMEM_VBUF_BYTES + SMEM_ATTN_BYTES)

// Packed f32x2 FMA: acc = v * a + acc
__device__ __forceinline__ void fma2(unsigned long long& acc,
                                     unsigned long long v,
                                     unsigned long long a) {
    asm("fma.rn.f32x2 %0, %1, %2, %0;" : "+l"(acc) : "l"(v), "l"(a));
}
// Duplicate one fp32 into both lanes of an f32x2 register pair (alu pipe).
__device__ __forceinline__ unsigned long long dup2(float w) {
    unsigned long long r;
    asm("mov.b64 %0, {%1, %1};" : "=l"(r) : "f"(w));
    return r;
}
// 16B async copy global -> shared (bypasses register file, deep MLP)
__device__ __forceinline__ void cp_async16(float* smem_dst, const float* gsrc) {
    unsigned s = (unsigned)__cvta_generic_to_shared(smem_dst);
    asm volatile("cp.async.cg.shared.global [%0], [%1], 16;" :: "r"(s), "l"(gsrc));
}
__device__ __forceinline__ void cp_commit() {
    asm volatile("cp.async.commit_group;");
}
template <int N>
__device__ __forceinline__ void cp_wait() {
    asm volatile("cp.async.wait_group %0;" :: "n"(N));
}

// ---------------------------------------------------------------------------
// Fused kernel: softmax + k-chunk double-buffered weighted sum + transpose +
// residual add. Grid: (S/SI, F/FI, B) = (16,16,8) = 2048 blocks, 256 thr.
// cp.async prefetch of V chunk c+1 overlaps the FMA loop on chunk c.
// ---------------------------------------------------------------------------
__global__ void __launch_bounds__(NT, 3)
fusion_kernel(const float* __restrict__ tgt,
              const float* __restrict__ V,
              const float* __restrict__ corr,
              const int*   __restrict__ tIdx,
              const int*   __restrict__ rIdx,
              float* __restrict__ out) {
    extern __shared__ char smem[];
    float* Vb[2] = { (float*)smem, (float*)(smem + SMEM_VBUF_BYTES) };
    float* attnF = (float*)(smem + 2 * SMEM_VBUF_BYTES);   // [K][T]
    float* stg   = (float*)smem;                            // overlays Vb after loop

    const int b   = blockIdx.z;
    const int f0  = blockIdx.y * FI;
    const int s0  = blockIdx.x * SI;
    const int tid = threadIdx.x;
    const int wid  = tid >> 5;
    const int lane = tid & 31;

    const float* Vg = V + (long)b * K_ * F_ * S_ + (long)f0 * S_ + s0;

    // --- prefetch chunk 0 (issues before softmax; latency hidden under it) ---
    {
        #pragma unroll
        for (int i = tid; i < KC * FI * (SI / 4); i += NT) {
            int k  = i / (FI * (SI / 4));
            int f  = (i / (SI / 4)) % FI;
            int s4 = i % (SI / 4);
            cp_async16(Vb[0] + (k * FI + f) * SI + s4 * 4,
                       Vg + ((long)k * F_ + f) * S_ + s4 * 4);
        }
        cp_commit();
    }

    // --- softmax: 8 warps x 4 t's each, gather from L2-hot corr ---
    {
        int c0 = rIdx[lane];
        int c1 = rIdx[lane + 32];
        #pragma unroll
        for (int t = wid; t < T_; t += (NT / 32)) {
            int row = tIdx[b * T_ + t];
            float v0 = __ldg(corr + row * N_ + c0);
            float v1 = __ldg(corr + row * N_ + c1);
            float m = fmaxf(v0, v1);
            #pragma unroll
            for (int off = 16; off > 0; off >>= 1)
                m = fmaxf(m, __shfl_xor_sync(0xffffffffu, m, off));
            float e0 = expf(v0 - m);
            float e1 = expf(v1 - m);
            float s = e0 + e1;
            #pragma unroll
            for (int off = 16; off > 0; off >>= 1)
                s += __shfl_xor_sync(0xffffffffu, s, off);
            float inv = 1.0f / s;
            attnF[lane * T_ + t]        = e0 * inv;
            attnF[(lane + 32) * T_ + t] = e1 * inv;
        }
    }

    // --- main loop: double-buffered k-chunks ---
    const int sg = tid & 7;           // 0..7 : s-group (4 s each)
    const int fl = (tid >> 3) & 7;    // 0..7 : f within tile
    const int tq = tid >> 6;          // 0..3 : t-quadrant
    const int t0 = tq * TG;

    unsigned long long acc[TG][2];
    #pragma unroll
    for (int j = 0; j < TG; ++j) { acc[j][0] = 0ULL; acc[j][1] = 0ULL; }

    #pragma unroll
    for (int c = 0; c < NCHUNK; ++c) {
        // prefetch next chunk into the other buffer
        if (c + 1 < NCHUNK) {
            float* dst = Vb[(c + 1) & 1];
            const float* src = Vg + (long)(c + 1) * KC * F_ * S_;
            #pragma unroll
            for (int i = tid; i < KC * FI * (SI / 4); i += NT) {
                int k  = i / (FI * (SI / 4));
                int f  = (i / (SI / 4)) % FI;
                int s4 = i % (SI / 4);
                cp_async16(dst + (k * FI + f) * SI + s4 * 4,
                           src + ((long)k * F_ + f) * S_ + s4 * 4);
            }
            cp_commit();
            cp_wait<1>();   // chunk c resident (one group still in flight)
        } else {
            cp_wait<0>();
        }
        __syncthreads();    // data visible to all; also covers attnF on c==0

        const float* Vc = Vb[c & 1];
        const float* aF = attnF + c * KC * T_;
        #pragma unroll 4
        for (int k = 0; k < KC; ++k) {
            ulonglong2 v = *(const ulonglong2*)(Vc + (k * FI + fl) * SI + sg * 4);
            float4 wlo = *(const float4*)(aF + k * T_ + t0);      // broadcast
            float4 whi = *(const float4*)(aF + k * T_ + t0 + 4);  // broadcast
            unsigned long long a0 = dup2(wlo.x), a1 = dup2(wlo.y);
            unsigned long long a2 = dup2(wlo.z), a3 = dup2(wlo.w);
            unsigned long long a4 = dup2(whi.x), a5 = dup2(whi.y);
            unsigned long long a6 = dup2(whi.z), a7 = dup2(whi.w);
            fma2(acc[0][0], v.x, a0); fma2(acc[0][1], v.y, a0);
            fma2(acc[1][0], v.x, a1); fma2(acc[1][1], v.y, a1);
            fma2(acc[2][0], v.x, a2); fma2(acc[2][1], v.y, a2);
            fma2(acc[3][0], v.x, a3); fma2(acc[3][1], v.y, a3);
            fma2(acc[4][0], v.x, a4); fma2(acc[4][1], v.y, a4);
            fma2(acc[5][0], v.x, a5); fma2(acc[5][1], v.y, a5);
            fma2(acc[6][0], v.x, a6); fma2(acc[6][1], v.y, a6);
            fma2(acc[7][0], v.x, a7); fma2(acc[7][1], v.y, a7);
        }
        __syncthreads();    // all reads of buf (c&1) done before it is refilled
    }

    // --- stage to smem [t][s][FI+1] (overlays V buffers; dead now) ---
    #pragma unroll
    for (int j = 0; j < TG; ++j) {
        #pragma unroll
        for (int p = 0; p < 2; ++p) {
            unsigned long long a = acc[j][p];
            float lo = __uint_as_float((unsigned)(a & 0xffffffffULL));
            float hi = __uint_as_float((unsigned)(a >> 32));
            int s = sg * 4 + p * 2;
            stg[((t0 + j) * SI + s)     * (FI + 1) + fl] = lo;
            stg[((t0 + j) * SI + s + 1) * (FI + 1) + fl] = hi;
        }
    }
    __syncthreads();

    // --- coalesced epilogue: f fastest -> full 32B sectors ---
    #pragma unroll
    for (int i = tid; i < T_ * SI * FI; i += NT) {
        int f = i & (FI - 1);
        int s = (i >> 3) & (SI - 1);
        int t = i >> 8;
        float c = stg[(t * SI + s) * (FI + 1) + f];
        long gi = (((long)b * T_ + t) * S_ + s0 + s) * F_ + f0 + f;
        out[gi] = tgt[gi] + c;
    }
}

// ---------------------------------------------------------------------------
extern "C" void kernel_launch(void* const* d_in, const int* in_sizes, int n_in,
                              void* d_out, int out_size) {
    const float* tgt  = nullptr;   // 16777216
    const float* V    = nullptr;   // 33554432
    const float* corr = nullptr;   // 40000
    const int*   tIdx = nullptr;   // 256   (int32: jax x64 disabled)
    const int*   rIdx = nullptr;   // 64

    for (int i = 0; i < n_in; ++i) {
        switch (in_sizes[i]) {
            case 16777216: tgt  = (const float*)d_in[i]; break;
            case 33554432: V    = (const float*)d_in[i]; break;
            case 40000:    corr = (const float*)d_in[i]; break;
            case 256:      tIdx = (const int*)d_in[i]; break;
            case 64:       rIdx = (const int*)d_in[i]; break;
            default: break;
        }
    }

    cudaFuncSetAttribute(fusion_kernel,
                         cudaFuncAttributeMaxDynamicSharedMemorySize,
                         SMEM_TOTAL);

    dim3 grid(S_ / SI, F_ / FI, B_);
    fusion_kernel<<<grid, NT, SMEM_TOTAL>>>(tgt, V, corr, tIdx, rIdx, (float*)d_out);
}

// round 6
// speedup vs baseline: 2.2830x; 1.0248x over previous
#include <cuda_runtime.h>
#include <cuda_bf16.h>

// Problem constants
#define B_  8
#define T_  32
#define S_  512
#define F_  128
#define K_  64
#define N_  200

// Tiling
#define SI  32          // s-tile
#define FI  8           // f-tile
#define NT  128         // threads per block (4 warps)
#define KC  16          // k's per pipeline chunk
#define NCHUNK (K_/KC)  // 4
#define NP  8           // t-pairs per thread (16 t's)

// SMEM (bytes):
//   Vbuf:  2 x KC*FI*SI floats = 2 x 16384 = 32768 (double buffer)
//   attnF: K*T floats          = 8192  (non-duplicated)
//   stgU:  (T/2)*SI*9 ull      = 36864 (overlays Vbuf + low part of attnF)
#define SMEM_VBUF_BYTES  (KC*FI*SI*4)
#define SMEM_ATTN_BYTES  (K_*T_*4)
#define SMEM_TOTAL       (2*SMEM_VBUF_BYTES + SMEM_ATTN_BYTES)

typedef unsigned long long ull;

// Packed f32x2 FMA: acc = v * a + acc   (lanes = two adjacent t's)
__device__ __forceinline__ void fma2(ull& acc, ull v, ull a) {
    asm("fma.rn.f32x2 %0, %1, %2, %0;" : "+l"(acc) : "l"(v), "l"(a));
}
// Duplicate one fp32 into both lanes of an f32x2 register pair.
__device__ __forceinline__ ull dup2(float w) {
    ull r;
    asm("mov.b64 %0, {%1, %1};" : "=l"(r) : "f"(w));
    return r;
}
// 16B async copy global -> shared
__device__ __forceinline__ void cp_async16(float* smem_dst, const float* gsrc) {
    unsigned s = (unsigned)__cvta_generic_to_shared(smem_dst);
    asm volatile("cp.async.cg.shared.global [%0], [%1], 16;" :: "r"(s), "l"(gsrc));
}
__device__ __forceinline__ void cp_commit() {
    asm volatile("cp.async.commit_group;");
}
template <int N>
__device__ __forceinline__ void cp_wait() {
    asm volatile("cp.async.wait_group %0;" :: "n"(N));
}

// ---------------------------------------------------------------------------
// Grid: (S/SI, F/FI, B) = (16,16,8) = 2048 blocks, 128 threads, 4 CTAs/SM.
// Thread (sg, fl, tq): 4 s x 1 f x 16 t (as 8 f32x2 t-pairs).
// ---------------------------------------------------------------------------
__global__ void __launch_bounds__(NT, 4)
fusion_kernel(const float* __restrict__ tgt,
              const float* __restrict__ V,
              const float* __restrict__ corr,
              const int*   __restrict__ tIdx,
              const int*   __restrict__ rIdx,
              float* __restrict__ out) {
    extern __shared__ char smem[];
    float* Vb[2] = { (float*)smem, (float*)(smem + SMEM_VBUF_BYTES) };
    float* attnF = (float*)(smem + 2 * SMEM_VBUF_BYTES);   // [K][T]
    ull*   stgU  = (ull*)smem;                              // overlay after loop

    const int b   = blockIdx.z;
    const int f0  = blockIdx.y * FI;
    const int s0  = blockIdx.x * SI;
    const int tid = threadIdx.x;
    const int wid  = tid >> 5;
    const int lane = tid & 31;

    const float* Vg = V + (long)b * K_ * F_ * S_ + (long)f0 * S_ + s0;

    // --- prefetch chunk 0 (latency hidden under softmax) ---
    {
        #pragma unroll
        for (int i = tid; i < KC * FI * (SI / 4); i += NT) {
            int k  = i / (FI * (SI / 4));
            int f  = (i / (SI / 4)) % FI;
            int s4 = i % (SI / 4);
            cp_async16(Vb[0] + (k * FI + f) * SI + s4 * 4,
                       Vg + ((long)k * F_ + f) * S_ + s4 * 4);
        }
        cp_commit();
    }

    // --- softmax: 4 warps x 8 t's each ---
    {
        int c0 = rIdx[lane];
        int c1 = rIdx[lane + 32];
        #pragma unroll
        for (int t = wid; t < T_; t += (NT / 32)) {
            int row = tIdx[b * T_ + t];
            float v0 = __ldg(corr + row * N_ + c0);
            float v1 = __ldg(corr + row * N_ + c1);
            float m = fmaxf(v0, v1);
            #pragma unroll
            for (int off = 16; off > 0; off >>= 1)
                m = fmaxf(m, __shfl_xor_sync(0xffffffffu, m, off));
            float e0 = expf(v0 - m);
            float e1 = expf(v1 - m);
            float s = e0 + e1;
            #pragma unroll
            for (int off = 16; off > 0; off >>= 1)
                s += __shfl_xor_sync(0xffffffffu, s, off);
            float inv = 1.0f / s;
            attnF[lane * T_ + t]        = e0 * inv;
            attnF[(lane + 32) * T_ + t] = e1 * inv;
        }
    }

    // --- main loop ---
    const int sg = tid & 7;           // 0..7 : s-group (4 s each)
    const int fl = (tid >> 3) & 7;    // 0..7 : f within tile
    const int tq = tid >> 6;          // 0..1 : t-half
    const int t0 = tq * 16;

    ull acc[NP][4];
    #pragma unroll
    for (int p = 0; p < NP; ++p)
        #pragma unroll
        for (int si = 0; si < 4; ++si) acc[p][si] = 0ULL;

    #pragma unroll
    for (int c = 0; c < NCHUNK; ++c) {
        if (c + 1 < NCHUNK) {
            float* dst = Vb[(c + 1) & 1];
            const float* src = Vg + (long)(c + 1) * KC * F_ * S_;
            #pragma unroll
            for (int i = tid; i < KC * FI * (SI / 4); i += NT) {
                int k  = i / (FI * (SI / 4));
                int f  = (i / (SI / 4)) % FI;
                int s4 = i % (SI / 4);
                cp_async16(dst + (k * FI + f) * SI + s4 * 4,
                           src + ((long)k * F_ + f) * S_ + s4 * 4);
            }
            cp_commit();
            cp_wait<1>();   // chunk c resident
        } else {
            cp_wait<0>();
        }
        __syncthreads();    // also publishes attnF on c==0

        const float* Vc = Vb[c & 1];
        const float* aF = attnF + c * KC * T_;
        #pragma unroll 4
        for (int k = 0; k < KC; ++k) {
            float4 vf = *(const float4*)(Vc + (k * FI + fl) * SI + sg * 4);
            ull vd0 = dup2(vf.x), vd1 = dup2(vf.y);
            ull vd2 = dup2(vf.z), vd3 = dup2(vf.w);
            // attn t-pairs, non-duplicated, broadcast loads
            ulonglong2 a01 = *(const ulonglong2*)(aF + k * T_ + t0);
            ulonglong2 a23 = *(const ulonglong2*)(aF + k * T_ + t0 + 4);
            ulonglong2 a45 = *(const ulonglong2*)(aF + k * T_ + t0 + 8);
            ulonglong2 a67 = *(const ulonglong2*)(aF + k * T_ + t0 + 12);
            fma2(acc[0][0], vd0, a01.x); fma2(acc[0][1], vd1, a01.x);
            fma2(acc[0][2], vd2, a01.x); fma2(acc[0][3], vd3, a01.x);
            fma2(acc[1][0], vd0, a01.y); fma2(acc[1][1], vd1, a01.y);
            fma2(acc[1][2], vd2, a01.y); fma2(acc[1][3], vd3, a01.y);
            fma2(acc[2][0], vd0, a23.x); fma2(acc[2][1], vd1, a23.x);
            fma2(acc[2][2], vd2, a23.x); fma2(acc[2][3], vd3, a23.x);
            fma2(acc[3][0], vd0, a23.y); fma2(acc[3][1], vd1, a23.y);
            fma2(acc[3][2], vd2, a23.y); fma2(acc[3][3], vd3, a23.y);
            fma2(acc[4][0], vd0, a45.x); fma2(acc[4][1], vd1, a45.x);
            fma2(acc[4][2], vd2, a45.x); fma2(acc[4][3], vd3, a45.x);
            fma2(acc[5][0], vd0, a45.y); fma2(acc[5][1], vd1, a45.y);
            fma2(acc[5][2], vd2, a45.y); fma2(acc[5][3], vd3, a45.y);
            fma2(acc[6][0], vd0, a67.x); fma2(acc[6][1], vd1, a67.x);
            fma2(acc[6][2], vd2, a67.x); fma2(acc[6][3], vd3, a67.x);
            fma2(acc[7][0], vd0, a67.y); fma2(acc[7][1], vd1, a67.y);
            fma2(acc[7][2], vd2, a67.y); fma2(acc[7][3], vd3, a67.y);
        }
        __syncthreads();
    }

    // --- stage: stgU[tpair][s][9] (8 fl + 1 pad), STS.64 of acc pairs ---
    #pragma unroll
    for (int p = 0; p < NP; ++p) {
        int tp = tq * NP + p;
        #pragma unroll
        for (int si = 0; si < 4; ++si) {
            int s = sg * 4 + si;
            stgU[(tp * SI + s) * 9 + fl] = acc[p][si];
        }
    }
    __syncthreads();

    // --- epilogue: f-fastest float4 global read-modify-write ---
    const float* stgF = (const float*)stgU;
    #pragma unroll 4
    for (int i = tid; i < T_ * SI * (FI / 4); i += NT) {
        int g = i & 1;             // which float4 of the 8-f row
        int s = (i >> 1) & (SI - 1);
        int t = i >> 6;
        int base = ((t >> 1) * SI + s) * 18 + (t & 1);
        float4 c4;
        c4.x = stgF[base + 2 * (4 * g + 0)];
        c4.y = stgF[base + 2 * (4 * g + 1)];
        c4.z = stgF[base + 2 * (4 * g + 2)];
        c4.w = stgF[base + 2 * (4 * g + 3)];
        long gi = (((long)b * T_ + t) * S_ + s0 + s) * F_ + f0 + 4 * g;
        float4 t4 = *(const float4*)(tgt + gi);
        c4.x += t4.x; c4.y += t4.y; c4.z += t4.z; c4.w += t4.w;
        *(float4*)(out + gi) = c4;
    }
}

// ---------------------------------------------------------------------------
extern "C" void kernel_launch(void* const* d_in, const int* in_sizes, int n_in,
                              void* d_out, int out_size) {
    const float* tgt  = nullptr;   // 16777216
    const float* V    = nullptr;   // 33554432
    const float* corr = nullptr;   // 40000
    const int*   tIdx = nullptr;   // 256   (int32: jax x64 disabled)
    const int*   rIdx = nullptr;   // 64

    for (int i = 0; i < n_in; ++i) {
        switch (in_sizes[i]) {
            case 16777216: tgt  = (const float*)d_in[i]; break;
            case 33554432: V    = (const float*)d_in[i]; break;
            case 40000:    corr = (const float*)d_in[i]; break;
            case 256:      tIdx = (const int*)d_in[i]; break;
            case 64:       rIdx = (const int*)d_in[i]; break;
            default: break;
        }
    }

    cudaFuncSetAttribute(fusion_kernel,
                         cudaFuncAttributeMaxDynamicSharedMemorySize,
                         SMEM_TOTAL);

    dim3 grid(S_ / SI, F_ / FI, B_);
    fusion_kernel<<<grid, NT, SMEM_TOTAL>>>(tgt, V, corr, tIdx, rIdx, (float*)d_out);
}